// round 1
// baseline (speedup 1.0000x reference)
#include <cuda_runtime.h>
#include <math.h>

// Problem shape (fixed by reference setup_inputs)
#define BB 8
#define DD 64
#define HH 256
#define WW 512
#define HW (HH * WW)          // 131072
#define PIXELS (BB * HW)      // 1048576
#define DISP_STEP 2.0f

// Global accumulators (allocation-free scratch)
__device__ double              g_sum;
__device__ unsigned long long  g_cnt;

__global__ void sce_init_kernel() {
    g_sum = 0.0;
    g_cnt = 0ull;
}

// Each thread processes 4 consecutive-w pixels (float4 loads).
// Per pixel, over d: se = sum exp(x_d); spt = sum Pt_d; sptx = sum Pt_d * x_d
// entropy = log(se) - sptx/spt    (the 1/(2*DIVERSITY) factor cancels)
__global__ void __launch_bounds__(256)
sce_main_kernel(const float* __restrict__ sim, const float* __restrict__ gt) {
    const int tid = blockIdx.x * blockDim.x + threadIdx.x;
    const int p   = tid * 4;                       // base pixel index
    const int b   = p / HW;
    const int rem = p - b * HW;                    // h*W + w, multiple of 4

    const float4* simv =
        (const float4*)(sim + (size_t)b * DD * HW + rem);

    const float4 g = *(const float4*)(gt + p);
    float gtv[4] = {g.x, g.y, g.z, g.w};

    float se[4]   = {0.f, 0.f, 0.f, 0.f};
    float spt[4]  = {0.f, 0.f, 0.f, 0.f};
    float sptx[4] = {0.f, 0.f, 0.f, 0.f};

    #pragma unroll 8
    for (int d = 0; d < DD; ++d) {
        const float4 x = simv[(size_t)d * (HW / 4)];
        const float dd = DISP_STEP * (float)d;
        const float xs[4] = {x.x, x.y, x.z, x.w};
        #pragma unroll
        for (int j = 0; j < 4; ++j) {
            const float xx = xs[j];
            se[j] += __expf(xx);
            // exp(-inf) = 0 for unknown pixels -> harmless, masked later
            const float pt = __expf(-fabsf(gtv[j] - dd));
            spt[j]  += pt;
            sptx[j] += pt * xx;
        }
    }

    float local = 0.f;
    int   cnt   = 0;
    #pragma unroll
    for (int j = 0; j < 4; ++j) {
        if (isfinite(gtv[j])) {
            local += __logf(se[j]) - sptx[j] / spt[j];
            cnt   += 1;
        }
    }

    // Warp reduce
    #pragma unroll
    for (int o = 16; o > 0; o >>= 1) {
        local += __shfl_down_sync(0xffffffffu, local, o);
        cnt   += __shfl_down_sync(0xffffffffu, cnt, o);
    }

    __shared__ float ssum[8];
    __shared__ int   scnt[8];
    const int lane = threadIdx.x & 31;
    const int wid  = threadIdx.x >> 5;
    if (lane == 0) { ssum[wid] = local; scnt[wid] = cnt; }
    __syncthreads();

    if (wid == 0) {
        local = (lane < 8) ? ssum[lane] : 0.f;
        cnt   = (lane < 8) ? scnt[lane] : 0;
        #pragma unroll
        for (int o = 4; o > 0; o >>= 1) {
            local += __shfl_down_sync(0xffffffffu, local, o);
            cnt   += __shfl_down_sync(0xffffffffu, cnt, o);
        }
        if (lane == 0) {
            atomicAdd(&g_sum, (double)local);
            atomicAdd(&g_cnt, (unsigned long long)cnt);
        }
    }
}

__global__ void sce_final_kernel(float* __restrict__ out) {
    out[0] = (float)(g_sum / (double)g_cnt);
}

extern "C" void kernel_launch(void* const* d_in, const int* in_sizes, int n_in,
                              void* d_out, int out_size) {
    const float* sim = (const float*)d_in[0];
    const float* gt  = (const float*)d_in[1];
    float* out       = (float*)d_out;

    sce_init_kernel<<<1, 1>>>();
    const int threads = 256;
    const int blocks  = PIXELS / 4 / threads;   // 1024
    sce_main_kernel<<<blocks, threads>>>(sim, gt);
    sce_final_kernel<<<1, 1>>>(out);
}